// round 9
// baseline (speedup 1.0000x reference)
#include <cuda_runtime.h>
#include <cstdint>

// ---------------- problem constants ----------------
#define B_      2
#define S_      4096
#define H_      2048
#define NH_     16
#define NKV_    4
#define D_      128
#define BS_     64
#define KB_     (S_ / BS_)
#define NGLOB_  4
#define NLOCAL_ 8
#define NSEL_   (NGLOB_ + NLOCAL_)
#define STRIDE_ 16
#define NTOK_   (B_ * S_)       // 8192
#define QDIM_   (NH_ * D_)      // 2048
#define KVDIM_  (NKV_ * D_)     // 512
#define SCALE_  0.088388347648318447f
#define NEG_    (-1000000000.0f)

// ---------------- scratch ---------------------------------------------------
__device__ float    g_q[(size_t)NTOK_ * QDIM_];
__device__ float    g_k[(size_t)NTOK_ * KVDIM_];
__device__ float    g_v[(size_t)NTOK_ * KVDIM_];
__device__ float    g_attn[(size_t)NTOK_ * QDIM_];  // tf32 bits
__device__ uint32_t g_xt[(size_t)NTOK_ * H_];       // X in tf32
__device__ uint32_t g_wt[(size_t)QDIM_ * H_];       // weights in tf32

// ---------------- helpers ---------------------------------------------------
__device__ __forceinline__ uint32_t f2tf32(float x) {
    uint32_t u;
    asm("cvt.rna.tf32.f32 %0, %1;" : "=r"(u) : "f"(x));
    return u;
}
__device__ __forceinline__ void split_tf32(float x, uint32_t& hi, uint32_t& lo) {
    hi = f2tf32(x);
    lo = f2tf32(x - __uint_as_float(hi));
}
__device__ __forceinline__ void mma_tf32(float* c, const uint32_t* a, const uint32_t* b) {
    asm volatile(
        "mma.sync.aligned.m16n8k8.row.col.f32.tf32.tf32.f32 "
        "{%0,%1,%2,%3}, {%4,%5,%6,%7}, {%8,%9}, {%0,%1,%2,%3};\n"
        : "+f"(c[0]), "+f"(c[1]), "+f"(c[2]), "+f"(c[3])
        : "r"(a[0]), "r"(a[1]), "r"(a[2]), "r"(a[3]), "r"(b[0]), "r"(b[1]));
}
__device__ __forceinline__ void cp_async16(uint32_t saddr, const void* gptr) {
    asm volatile("cp.async.cg.shared.global [%0], [%1], 16;\n"
                 :: "r"(saddr), "l"(gptr));
}

// ---------------- fp32 -> tf32 conversion -----------------------------------
__global__ void cvt_tf32_kernel(const float* __restrict__ in,
                                uint32_t* __restrict__ out, int n4)
{
    int i = blockIdx.x * blockDim.x + threadIdx.x;
    if (i >= n4) return;
    float4 v = ((const float4*)in)[i];
    uint4 o;
    o.x = f2tf32(v.x); o.y = f2tf32(v.y);
    o.z = f2tf32(v.z); o.w = f2tf32(v.w);
    ((uint4*)out)[i] = o;
}

// ---------------- big-tile pipelined tf32 GEMM ------------------------------
//  C[M,N] = A[M,K] @ B[N,K]^T ; A,B tf32 bits, K contiguous.
//  CTA tile 128x256, BK=16, 3-stage cp.async, 256 threads = 8 warps (2x4),
//  warp tile 64x64 (4x8 m16n8k8). Output split: cols >= Nsplit go to C1.
#define GBM_  128
#define GBN_  256
#define GBK_  16
#define GSTG_ 3
#define LDAG_ 20
#define A_ST_WORDS (GBM_ * LDAG_)     // 2560
#define B_ST_WORDS (GBN_ * LDAG_)     // 5120
#define ST_WORDS   (A_ST_WORDS + B_ST_WORDS)
#define GSMEM_BYTES (GSTG_ * ST_WORDS * 4)   // 92160

__global__ void __launch_bounds__(256, 1)
gemm_tf32_big(const uint32_t* __restrict__ A, const uint32_t* __restrict__ B,
              float* __restrict__ C0, float* __restrict__ C1,
              int Nsplit, int ldc, int K)
{
    extern __shared__ uint32_t smg[];

    const size_t bm = (size_t)blockIdx.y * GBM_;
    const size_t bn = (size_t)blockIdx.x * GBN_;
    const int t = threadIdx.x;
    const int lane = t & 31, warp = t >> 5;
    const int g  = lane >> 2, tg = lane & 3;
    const int wm = (warp >> 2) * 64;      // 0 or 64
    const int wn = (warp & 3) * 64;       // 0,64,128,192

    float acc[4][8][4];
#pragma unroll
    for (int mi = 0; mi < 4; mi++)
#pragma unroll
        for (int ni = 0; ni < 8; ni++)
#pragma unroll
            for (int c = 0; c < 4; c++) acc[mi][ni][c] = 0.0f;

    auto load_stage = [&](int s, int i) {
        uint32_t* as = smg + s * ST_WORDS;
        uint32_t* bs = as + A_ST_WORDS;
        const int k0 = i * GBK_;
        // A: 128 rows x 4 chunks = 512 chunks; 2 per thread
#pragma unroll
        for (int j = 0; j < 2; j++) {
            int idx = t + j * 256;
            int row = idx >> 2, kc = (idx & 3) << 2;
            uint32_t sa = (uint32_t)__cvta_generic_to_shared(&as[row * LDAG_ + kc]);
            cp_async16(sa, A + (bm + row) * (size_t)K + k0 + kc);
        }
        // B: 256 rows x 4 chunks = 1024 chunks; 4 per thread
#pragma unroll
        for (int j = 0; j < 4; j++) {
            int idx = t + j * 256;
            int row = idx >> 2, kc = (idx & 3) << 2;
            uint32_t sb = (uint32_t)__cvta_generic_to_shared(&bs[row * LDAG_ + kc]);
            cp_async16(sb, B + (bn + row) * (size_t)K + k0 + kc);
        }
        asm volatile("cp.async.commit_group;\n");
    };

    auto compute_stage = [&](int s) {
        const uint32_t* as = smg + s * ST_WORDS;
        const uint32_t* bs = as + A_ST_WORDS;
#pragma unroll
        for (int kk = 0; kk < 2; kk++) {
            const int kb = kk * 8;
            uint32_t a[4][4];
#pragma unroll
            for (int mi = 0; mi < 4; mi++) {
                const int m0 = wm + mi * 16;
                a[mi][0] = as[(m0 + g) * LDAG_ + kb + tg];
                a[mi][1] = as[(m0 + g + 8) * LDAG_ + kb + tg];
                a[mi][2] = as[(m0 + g) * LDAG_ + kb + tg + 4];
                a[mi][3] = as[(m0 + g + 8) * LDAG_ + kb + tg + 4];
            }
            uint32_t bf[8][2];
#pragma unroll
            for (int ni = 0; ni < 8; ni++) {
                const int n0 = wn + ni * 8;
                bf[ni][0] = bs[(n0 + g) * LDAG_ + kb + tg];
                bf[ni][1] = bs[(n0 + g) * LDAG_ + kb + tg + 4];
            }
#pragma unroll
            for (int mi = 0; mi < 4; mi++)
#pragma unroll
                for (int ni = 0; ni < 8; ni++)
                    mma_tf32(acc[mi][ni], a[mi], bf[ni]);
        }
    };

    const int niter = K / GBK_;
    load_stage(0, 0);
    load_stage(1, 1);

    for (int i = 0; i < niter - 1; i++) {
        asm volatile("cp.async.wait_group 1;\n" ::: "memory");
        __syncthreads();
        if (i + 2 < niter) load_stage((i + 2) % GSTG_, i + 2);
        compute_stage(i % GSTG_);
    }
    asm volatile("cp.async.wait_group 0;\n" ::: "memory");
    __syncthreads();
    compute_stage((niter - 1) % GSTG_);

    // epilogue: pick target matrix by column split
    float* C = C0;
    int cb = (int)bn;
    if (cb >= Nsplit) { C = C1; cb -= Nsplit; }

#pragma unroll
    for (int mi = 0; mi < 4; mi++) {
        const size_t row = bm + wm + mi * 16 + g;
#pragma unroll
        for (int ni = 0; ni < 8; ni++) {
            const int col = cb + wn + ni * 8 + 2 * tg;
            float* cp0 = C + row * ldc + col;
            float* cp1 = cp0 + (size_t)8 * ldc;
            *(float2*)cp0 = make_float2(acc[mi][ni][0], acc[mi][ni][1]);
            *(float2*)cp1 = make_float2(acc[mi][ni][2], acc[mi][ni][3]);
        }
    }
}

// ---------------- RoPE (in-place on g_q, g_k) -------------------------------
__global__ void rope_kernel(const float* __restrict__ cosp,
                            const float* __restrict__ sinp)
{
    int idx = blockIdx.x * blockDim.x + threadIdx.x;
    const int total = NTOK_ * (NH_ + NKV_) * (D_ / 2);
    if (idx >= total) return;

    int d    = idx % (D_ / 2);
    int rest = idx / (D_ / 2);
    int h    = rest % (NH_ + NKV_);
    int tok  = rest / (NH_ + NKV_);

    float c1 = cosp[(size_t)tok * D_ + d];
    float s1 = sinp[(size_t)tok * D_ + d];
    float c2 = cosp[(size_t)tok * D_ + d + D_ / 2];
    float s2 = sinp[(size_t)tok * D_ + d + D_ / 2];

    float* buf;
    if (h < NH_) buf = g_q + (size_t)tok * QDIM_ + h * D_;
    else         buf = g_k + (size_t)tok * KVDIM_ + (h - NH_) * D_;

    float x1 = buf[d];
    float x2 = buf[d + D_ / 2];
    buf[d]           = x1 * c1 - x2 * s1;
    buf[d + D_ / 2]  = x2 * c2 + x1 * s2;
}

// ---------------- block-sparse attention (mma.sync, 3xTF32) -----------------
#define LDQ_   132
#define LDSS_  68
#define AT_SMEM_FLOATS (64*LDQ_ + 64*LDQ_ + 64*LDSS_ + 128 + 128 + 3*64)
#define AT_SMEM_BYTES  (AT_SMEM_FLOATS * 4)

__global__ void __launch_bounds__(256, 2)
attn_kernel()
{
    extern __shared__ float sm[];
    float* Qs   = sm;
    float* KVs  = Qs + 64 * LDQ_;
    float* Ss   = KVs + 64 * LDQ_;
    float* wmax = Ss + 64 * LDSS_;
    float* wsum = wmax + 128;
    float* rowm = wsum + 128;
    float* rowl = rowm + 64;
    float* rowf = rowl + 64;
    __shared__ int sel_s[NSEL_];
    __shared__ int keep_s[NSEL_];

    const int qid = blockIdx.x;
    const int h   = blockIdx.y;
    const int b   = blockIdx.z;
    const int t   = threadIdx.x;
    const int kvh = h / (NH_ / NKV_);

    const int warp = t >> 5, lane = t & 31;
    const int g  = lane >> 2;
    const int tg = lane & 3;
    const int wm  = (warp >> 1) * 16;
    const int nh  = warp & 1;
    const int wn  = nh * 32;
    const int wn2 = nh * 64;
    const int row0 = wm + g;
    const int row1 = wm + g + 8;

    const float* qptr = g_q + ((size_t)(b * S_ + qid * BS_)) * QDIM_ + h * D_;
    for (int i4 = t; i4 < 64 * 32; i4 += 256) {
        int r = i4 >> 5, d4 = (i4 & 31) << 2;
        *(float4*)&Qs[r * LDQ_ + d4] = *(const float4*)(qptr + (size_t)r * QDIM_ + d4);
    }

    if (t < NSEL_) {
        int s;
        if (t < NGLOB_) { s = t * STRIDE_; if (s > KB_ - 1) s = KB_ - 1; }
        else            { int j = t - NGLOB_; s = qid - (NLOCAL_ - 1) + j;
                          s = s < 0 ? 0 : (s > KB_ - 1 ? KB_ - 1 : s); }
        bool valid = (s <= qid);
        bool dup = false;
        for (int jj = 0; jj < t; jj++) {
            int sj;
            if (jj < NGLOB_) { sj = jj * STRIDE_; if (sj > KB_ - 1) sj = KB_ - 1; }
            else             { int j2 = jj - NGLOB_; sj = qid - (NLOCAL_ - 1) + j2;
                               sj = sj < 0 ? 0 : (sj > KB_ - 1 ? KB_ - 1 : sj); }
            if (sj == s) dup = true;
        }
        sel_s[t]  = s;
        keep_s[t] = (valid && !dup) ? 1 : 0;
    }
    if (t < 64) { rowm[t] = -1e30f; rowl[t] = 0.0f; }

    float o[8][4];
#pragma unroll
    for (int ni = 0; ni < 8; ni++)
#pragma unroll
        for (int c = 0; c < 4; c++) o[ni][c] = 0.0f;

    __syncthreads();

    for (int bi = 0; bi < NSEL_; bi++) {
        if (!keep_s[bi]) continue;
        const int kblk = sel_s[bi];
        const bool diag = (kblk == qid);

        const float* kptr = g_k + ((size_t)(b * S_ + kblk * BS_)) * KVDIM_ + kvh * D_;
        for (int i4 = t; i4 < 64 * 32; i4 += 256) {
            int r = i4 >> 5, d4 = (i4 & 31) << 2;
            *(float4*)&KVs[r * LDQ_ + d4] = *(const float4*)(kptr + (size_t)r * KVDIM_ + d4);
        }
        __syncthreads();

        float sacc[4][4];
#pragma unroll
        for (int ni = 0; ni < 4; ni++)
#pragma unroll
            for (int c = 0; c < 4; c++) sacc[ni][c] = 0.0f;

#pragma unroll
        for (int ks = 0; ks < 16; ks++) {
            const int kb = ks * 8;
            uint32_t ahi[4], alo[4];
            split_tf32(Qs[row0 * LDQ_ + kb + tg],     ahi[0], alo[0]);
            split_tf32(Qs[row1 * LDQ_ + kb + tg],     ahi[1], alo[1]);
            split_tf32(Qs[row0 * LDQ_ + kb + tg + 4], ahi[2], alo[2]);
            split_tf32(Qs[row1 * LDQ_ + kb + tg + 4], ahi[3], alo[3]);
#pragma unroll
            for (int ni = 0; ni < 4; ni++) {
                const int n = wn + ni * 8 + g;
                uint32_t bhi[2], blo[2];
                split_tf32(KVs[n * LDQ_ + kb + tg],     bhi[0], blo[0]);
                split_tf32(KVs[n * LDQ_ + kb + tg + 4], bhi[1], blo[1]);
                mma_tf32(sacc[ni], ahi, bhi);
                mma_tf32(sacc[ni], ahi, blo);
                mma_tf32(sacc[ni], alo, bhi);
            }
        }

        float pm0 = -1e30f, pm1 = -1e30f;
#pragma unroll
        for (int ni = 0; ni < 4; ni++) {
            const int colb = wn + ni * 8 + 2 * tg;
#pragma unroll
            for (int c = 0; c < 4; c++) {
                const int col = colb + (c & 1);
                const int row = (c < 2) ? row0 : row1;
                float v = sacc[ni][c] * SCALE_;
                if (diag && col > row) v += NEG_;
                sacc[ni][c] = v;
                if (c < 2) pm0 = fmaxf(pm0, v);
                else       pm1 = fmaxf(pm1, v);
            }
        }
        pm0 = fmaxf(pm0, __shfl_xor_sync(0xffffffff, pm0, 1));
        pm0 = fmaxf(pm0, __shfl_xor_sync(0xffffffff, pm0, 2));
        pm1 = fmaxf(pm1, __shfl_xor_sync(0xffffffff, pm1, 1));
        pm1 = fmaxf(pm1, __shfl_xor_sync(0xffffffff, pm1, 2));
        if (tg == 0) {
            wmax[nh * 64 + row0] = pm0;
            wmax[nh * 64 + row1] = pm1;
        }
        __syncthreads();

        float mx0 = fmaxf(fmaxf(wmax[row0], wmax[64 + row0]), rowm[row0]);
        float mx1 = fmaxf(fmaxf(wmax[row1], wmax[64 + row1]), rowm[row1]);
        float ps0 = 0.0f, ps1 = 0.0f;
#pragma unroll
        for (int ni = 0; ni < 4; ni++) {
#pragma unroll
            for (int c = 0; c < 4; c++) {
                float p = __expf(sacc[ni][c] - ((c < 2) ? mx0 : mx1));
                sacc[ni][c] = p;
                if (c < 2) ps0 += p; else ps1 += p;
            }
        }
        ps0 += __shfl_xor_sync(0xffffffff, ps0, 1);
        ps0 += __shfl_xor_sync(0xffffffff, ps0, 2);
        ps1 += __shfl_xor_sync(0xffffffff, ps1, 1);
        ps1 += __shfl_xor_sync(0xffffffff, ps1, 2);
        if (tg == 0) {
            wsum[nh * 64 + row0] = ps0;
            wsum[nh * 64 + row1] = ps1;
        }
        float mxt = 0.0f, ft = 0.0f;
        if (t < 64) {
            mxt = fmaxf(fmaxf(wmax[t], wmax[64 + t]), rowm[t]);
            ft  = __expf(rowm[t] - mxt);
            rowf[t] = ft;
        }
        __syncthreads();

        if (t < 64) {
            rowl[t] = rowl[t] * ft + wsum[t] + wsum[64 + t];
            rowm[t] = mxt;
        }

        {
            float f0 = rowf[row0], f1 = rowf[row1];
#pragma unroll
            for (int ni = 0; ni < 8; ni++) {
                o[ni][0] *= f0; o[ni][1] *= f0;
                o[ni][2] *= f1; o[ni][3] *= f1;
            }
        }
#pragma unroll
        for (int ni = 0; ni < 4; ni++) {
            const int colb = wn + ni * 8 + 2 * tg;
            *(float2*)&Ss[row0 * LDSS_ + colb] = make_float2(sacc[ni][0], sacc[ni][1]);
            *(float2*)&Ss[row1 * LDSS_ + colb] = make_float2(sacc[ni][2], sacc[ni][3]);
        }
        const float* vptr = g_v + ((size_t)(b * S_ + kblk * BS_)) * KVDIM_ + kvh * D_;
        for (int i4 = t; i4 < 64 * 32; i4 += 256) {
            int r = i4 >> 5, d4 = (i4 & 31) << 2;
            *(float4*)&KVs[r * LDQ_ + d4] = *(const float4*)(vptr + (size_t)r * KVDIM_ + d4);
        }
        __syncthreads();

#pragma unroll
        for (int ks = 0; ks < 8; ks++) {
            const int kb = ks * 8;
            uint32_t ahi[4], alo[4];
            split_tf32(Ss[row0 * LDSS_ + kb + tg],     ahi[0], alo[0]);
            split_tf32(Ss[row1 * LDSS_ + kb + tg],     ahi[1], alo[1]);
            split_tf32(Ss[row0 * LDSS_ + kb + tg + 4], ahi[2], alo[2]);
            split_tf32(Ss[row1 * LDSS_ + kb + tg + 4], ahi[3], alo[3]);
#pragma unroll
            for (int ni = 0; ni < 8; ni++) {
                const int n = wn2 + ni * 8 + g;
                uint32_t bhi[2], blo[2];
                split_tf32(KVs[(kb + tg) * LDQ_ + n],     bhi[0], blo[0]);
                split_tf32(KVs[(kb + tg + 4) * LDQ_ + n], bhi[1], blo[1]);
                mma_tf32(o[ni], ahi, bhi);
                mma_tf32(o[ni], ahi, blo);
                mma_tf32(o[ni], alo, bhi);
            }
        }
        __syncthreads();
    }

    const float invl0 = 1.0f / rowl[row0];
    const float invl1 = 1.0f / rowl[row1];
    float* ob0 = g_attn + ((size_t)(b * S_ + qid * BS_ + row0)) * QDIM_ + h * D_;
    float* ob1 = g_attn + ((size_t)(b * S_ + qid * BS_ + row1)) * QDIM_ + h * D_;
#pragma unroll
    for (int ni = 0; ni < 8; ni++) {
        const int col = wn2 + ni * 8 + 2 * tg;
        *(uint2*)(ob0 + col) = make_uint2(f2tf32(o[ni][0] * invl0),
                                          f2tf32(o[ni][1] * invl0));
        *(uint2*)(ob1 + col) = make_uint2(f2tf32(o[ni][2] * invl1),
                                          f2tf32(o[ni][3] * invl1));
    }
}

// ---------------- host launcher ---------------------------------------------
extern "C" void kernel_launch(void* const* d_in, const int* in_sizes, int n_in,
                              void* d_out, int out_size)
{
    const float* X    = (const float*)d_in[0];
    const float* cosp = (const float*)d_in[1];
    const float* sinp = (const float*)d_in[2];
    const float* Wq   = (const float*)d_in[3];
    const float* Wk   = (const float*)d_in[4];
    const float* Wv   = (const float*)d_in[5];
    const float* Wo   = (const float*)d_in[6];
    float* out = (float*)d_out;

    float *qb, *kb, *vb, *ab;
    uint32_t *xt, *wt;
    cudaGetSymbolAddress((void**)&qb, g_q);
    cudaGetSymbolAddress((void**)&kb, g_k);
    cudaGetSymbolAddress((void**)&vb, g_v);
    cudaGetSymbolAddress((void**)&ab, g_attn);
    cudaGetSymbolAddress((void**)&xt, g_xt);
    cudaGetSymbolAddress((void**)&wt, g_wt);

    cudaFuncSetAttribute(attn_kernel,
                         cudaFuncAttributeMaxDynamicSharedMemorySize,
                         AT_SMEM_BYTES);
    cudaFuncSetAttribute(gemm_tf32_big,
                         cudaFuncAttributeMaxDynamicSharedMemorySize,
                         GSMEM_BYTES);

    const int ct = 256;
    const int BIG = 1 << 30;

    // X -> tf32
    cvt_tf32_kernel<<<(NTOK_ * H_ / 4 + ct - 1) / ct, ct>>>(X, xt, NTOK_ * H_ / 4);

    // Q projection: C = X @ Wq^T  [8192 x 2048]
    cvt_tf32_kernel<<<(QDIM_ * H_ / 4 + ct - 1) / ct, ct>>>(Wq, wt, QDIM_ * H_ / 4);
    gemm_tf32_big<<<dim3(QDIM_ / GBN_, NTOK_ / GBM_), 256, GSMEM_BYTES>>>(
        xt, wt, qb, qb, BIG, QDIM_, H_);

    // Fused K+V projection: weights concatenated [1024 x 2048]
    cvt_tf32_kernel<<<(KVDIM_ * H_ / 4 + ct - 1) / ct, ct>>>(Wk, wt, KVDIM_ * H_ / 4);
    cvt_tf32_kernel<<<(KVDIM_ * H_ / 4 + ct - 1) / ct, ct>>>(
        Wv, wt + (size_t)KVDIM_ * H_, KVDIM_ * H_ / 4);
    gemm_tf32_big<<<dim3(2 * KVDIM_ / GBN_, NTOK_ / GBM_), 256, GSMEM_BYTES>>>(
        xt, wt, kb, vb, KVDIM_, KVDIM_, H_);

    // RoPE on Q and K
    int rope_total = NTOK_ * (NH_ + NKV_) * (D_ / 2);
    rope_kernel<<<(rope_total + 255) / 256, 256>>>(cosp, sinp);

    // block-sparse attention (writes tf32 bits to g_attn)
    attn_kernel<<<dim3(KB_, NH_, B_), 256, AT_SMEM_BYTES>>>();

    // O projection
    cvt_tf32_kernel<<<(H_ * QDIM_ / 4 + ct - 1) / ct, ct>>>(Wo, wt, H_ * QDIM_ / 4);
    gemm_tf32_big<<<dim3(H_ / GBN_, NTOK_ / GBM_), 256, GSMEM_BYTES>>>(
        (const uint32_t*)ab, wt, out, out, BIG, H_, QDIM_);
}

// round 10
// speedup vs baseline: 1.0631x; 1.0631x over previous
#include <cuda_runtime.h>
#include <cstdint>

// ---------------- problem constants ----------------
#define B_      2
#define S_      4096
#define H_      2048
#define NH_     16
#define NKV_    4
#define D_      128
#define BS_     64
#define KB_     (S_ / BS_)
#define NGLOB_  4
#define NLOCAL_ 8
#define NSEL_   (NGLOB_ + NLOCAL_)
#define STRIDE_ 16
#define NTOK_   (B_ * S_)       // 8192
#define QDIM_   (NH_ * D_)      // 2048
#define KVDIM_  (NKV_ * D_)     // 512
#define SCALE_  0.088388347648318447f
#define NEG_    (-1000000000.0f)

// ---------------- scratch ---------------------------------------------------
__device__ float    g_q[(size_t)NTOK_ * QDIM_];
__device__ float    g_k[(size_t)NTOK_ * KVDIM_];
__device__ float    g_v[(size_t)NTOK_ * KVDIM_];
__device__ float    g_attn[(size_t)NTOK_ * QDIM_];      // tf32 bits
__device__ uint32_t g_xt[(size_t)NTOK_ * H_];           // X in tf32
// weights in tf32: [Wq 4M][Wk 1M][Wv 1M][Wo 4M] words
#define WQ_OFF_ 0
#define WK_OFF_ ((size_t)QDIM_ * H_)
#define WV_OFF_ (WK_OFF_ + (size_t)KVDIM_ * H_)
#define WO_OFF_ (WV_OFF_ + (size_t)KVDIM_ * H_)
#define WT_WORDS_ (WO_OFF_ + (size_t)QDIM_ * H_)
__device__ uint32_t g_wt[WT_WORDS_];

// ---------------- helpers ---------------------------------------------------
__device__ __forceinline__ uint32_t f2tf32(float x) {
    uint32_t u;
    asm("cvt.rna.tf32.f32 %0, %1;" : "=r"(u) : "f"(x));
    return u;
}
__device__ __forceinline__ void split_tf32(float x, uint32_t& hi, uint32_t& lo) {
    hi = f2tf32(x);
    lo = f2tf32(x - __uint_as_float(hi));
}
__device__ __forceinline__ void mma_tf32(float* c, const uint32_t* a, const uint32_t* b) {
    asm volatile(
        "mma.sync.aligned.m16n8k8.row.col.f32.tf32.tf32.f32 "
        "{%0,%1,%2,%3}, {%4,%5,%6,%7}, {%8,%9}, {%0,%1,%2,%3};\n"
        : "+f"(c[0]), "+f"(c[1]), "+f"(c[2]), "+f"(c[3])
        : "r"(a[0]), "r"(a[1]), "r"(a[2]), "r"(a[3]), "r"(b[0]), "r"(b[1]));
}
__device__ __forceinline__ void cp_async16(uint32_t saddr, const void* gptr) {
    asm volatile("cp.async.cg.shared.global [%0], [%1], 16;\n"
                 :: "r"(saddr), "l"(gptr));
}

// ---------------- merged fp32 -> tf32 conversion ----------------------------
// converts X and all four weight matrices in one launch.
#define CVT_X4_   (NTOK_ * (H_ / 4))            // 4,194,304 float4s for X
#define CVT_WQ4_  (QDIM_ * (H_ / 4))            // 1,048,576
#define CVT_WK4_  (KVDIM_ * (H_ / 4))           //   262,144
#define CVT_TOT4_ (CVT_X4_ + CVT_WQ4_ + 2 * CVT_WK4_ + CVT_WQ4_)

__global__ void cvt_all_kernel(const float* __restrict__ X,
                               const float* __restrict__ Wq,
                               const float* __restrict__ Wk,
                               const float* __restrict__ Wv,
                               const float* __restrict__ Wo)
{
    int i = blockIdx.x * blockDim.x + threadIdx.x;
    if (i >= CVT_TOT4_) return;

    const float4* src;
    uint4* dst;
    if (i < CVT_X4_) {
        src = (const float4*)X + i;
        dst = (uint4*)g_xt + i;
    } else if (i < CVT_X4_ + CVT_WQ4_) {
        int j = i - CVT_X4_;
        src = (const float4*)Wq + j;
        dst = (uint4*)(g_wt + WQ_OFF_) + j;
    } else if (i < CVT_X4_ + CVT_WQ4_ + CVT_WK4_) {
        int j = i - CVT_X4_ - CVT_WQ4_;
        src = (const float4*)Wk + j;
        dst = (uint4*)(g_wt + WK_OFF_) + j;
    } else if (i < CVT_X4_ + CVT_WQ4_ + 2 * CVT_WK4_) {
        int j = i - CVT_X4_ - CVT_WQ4_ - CVT_WK4_;
        src = (const float4*)Wv + j;
        dst = (uint4*)(g_wt + WV_OFF_) + j;
    } else {
        int j = i - CVT_X4_ - CVT_WQ4_ - 2 * CVT_WK4_;
        src = (const float4*)Wo + j;
        dst = (uint4*)(g_wt + WO_OFF_) + j;
    }
    float4 v = *src;
    uint4 o;
    o.x = f2tf32(v.x); o.y = f2tf32(v.y);
    o.z = f2tf32(v.z); o.w = f2tf32(v.w);
    *dst = o;
}

// ---------------- pipelined tf32 GEMM (R4 config, 4 stages) -----------------
//  C[M,N] = A[M,K] @ B[N,K]^T ; A,B tf32 bits, K contiguous.
//  128x128 CTA tile, BK=16, 4-stage cp.async, 256 threads = 8 warps (2x4),
//  warp tile 64x32 (4x4 m16n8k8). Output columns >= Nsplit go to C1.
#define BKG_  16
#define LDAG_ 20
#define GSTG_ 4
#define ST_WORDS_ (2 * 128 * LDAG_)            // A+B per stage = 5120 words
#define GSMEM_BYTES (GSTG_ * ST_WORDS_ * 4)    // 81920

__global__ void __launch_bounds__(256, 2)
gemm_tf32_pipe(const uint32_t* __restrict__ A, const uint32_t* __restrict__ B,
               float* __restrict__ C0, float* __restrict__ C1,
               int Nsplit, int ldc, int K)
{
    extern __shared__ uint32_t smg[];

    const size_t bm = (size_t)blockIdx.y * 128;
    const size_t bn = (size_t)blockIdx.x * 128;
    const int t = threadIdx.x;
    const int lane = t & 31, warp = t >> 5;
    const int g  = lane >> 2, tg = lane & 3;
    const int wm = (warp >> 2) * 64;
    const int wn = (warp & 3) * 32;

    float acc[4][4][4];
#pragma unroll
    for (int mi = 0; mi < 4; mi++)
#pragma unroll
        for (int ni = 0; ni < 4; ni++)
#pragma unroll
            for (int c = 0; c < 4; c++) acc[mi][ni][c] = 0.0f;

    auto load_stage = [&](int s, int i) {
        uint32_t* as = smg + s * ST_WORDS_;
        uint32_t* bs = as + 128 * LDAG_;
        const int k0 = i * BKG_;
#pragma unroll
        for (int j = 0; j < 2; j++) {
            int idx = t + j * 256;
            int row = idx >> 2, kc = (idx & 3) << 2;
            uint32_t sa = (uint32_t)__cvta_generic_to_shared(&as[row * LDAG_ + kc]);
            cp_async16(sa, A + (bm + row) * (size_t)K + k0 + kc);
            uint32_t sb = (uint32_t)__cvta_generic_to_shared(&bs[row * LDAG_ + kc]);
            cp_async16(sb, B + (bn + row) * (size_t)K + k0 + kc);
        }
        asm volatile("cp.async.commit_group;\n");
    };

    auto compute_stage = [&](int s) {
        const uint32_t* as = smg + s * ST_WORDS_;
        const uint32_t* bs = as + 128 * LDAG_;
#pragma unroll
        for (int kk = 0; kk < 2; kk++) {
            const int kb = kk * 8;
            uint32_t a[4][4];
#pragma unroll
            for (int mi = 0; mi < 4; mi++) {
                const int m0 = wm + mi * 16;
                a[mi][0] = as[(m0 + g) * LDAG_ + kb + tg];
                a[mi][1] = as[(m0 + g + 8) * LDAG_ + kb + tg];
                a[mi][2] = as[(m0 + g) * LDAG_ + kb + tg + 4];
                a[mi][3] = as[(m0 + g + 8) * LDAG_ + kb + tg + 4];
            }
            uint32_t bf[4][2];
#pragma unroll
            for (int ni = 0; ni < 4; ni++) {
                const int n0 = wn + ni * 8;
                bf[ni][0] = bs[(n0 + g) * LDAG_ + kb + tg];
                bf[ni][1] = bs[(n0 + g) * LDAG_ + kb + tg + 4];
            }
#pragma unroll
            for (int mi = 0; mi < 4; mi++)
#pragma unroll
                for (int ni = 0; ni < 4; ni++)
                    mma_tf32(acc[mi][ni], a[mi], bf[ni]);
        }
    };

    const int niter = K / BKG_;
    load_stage(0, 0);
    load_stage(1, 1);
    load_stage(2, 2);

    for (int i = 0; i < niter - 1; i++) {
        asm volatile("cp.async.wait_group 2;\n" ::: "memory");
        __syncthreads();
        if (i + 3 < niter) load_stage((i + 3) % GSTG_, i + 3);
        compute_stage(i % GSTG_);
    }
    asm volatile("cp.async.wait_group 0;\n" ::: "memory");
    __syncthreads();
    compute_stage((niter - 1) % GSTG_);

    // epilogue: pick target matrix by column split
    float* C = C0;
    int cb = (int)bn;
    if (cb >= Nsplit) { C = C1; cb -= Nsplit; }

#pragma unroll
    for (int mi = 0; mi < 4; mi++) {
        const size_t row = bm + wm + mi * 16 + g;
#pragma unroll
        for (int ni = 0; ni < 4; ni++) {
            const int col = cb + wn + ni * 8 + 2 * tg;
            float* cp0 = C + row * ldc + col;
            float* cp1 = cp0 + (size_t)8 * ldc;
            *(float2*)cp0 = make_float2(acc[mi][ni][0], acc[mi][ni][1]);
            *(float2*)cp1 = make_float2(acc[mi][ni][2], acc[mi][ni][3]);
        }
    }
}

// ---------------- RoPE (in-place on g_q, g_k) -------------------------------
__global__ void rope_kernel(const float* __restrict__ cosp,
                            const float* __restrict__ sinp)
{
    int idx = blockIdx.x * blockDim.x + threadIdx.x;
    const int total = NTOK_ * (NH_ + NKV_) * (D_ / 2);
    if (idx >= total) return;

    int d    = idx % (D_ / 2);
    int rest = idx / (D_ / 2);
    int h    = rest % (NH_ + NKV_);
    int tok  = rest / (NH_ + NKV_);

    float c1 = cosp[(size_t)tok * D_ + d];
    float s1 = sinp[(size_t)tok * D_ + d];
    float c2 = cosp[(size_t)tok * D_ + d + D_ / 2];
    float s2 = sinp[(size_t)tok * D_ + d + D_ / 2];

    float* buf;
    if (h < NH_) buf = g_q + (size_t)tok * QDIM_ + h * D_;
    else         buf = g_k + (size_t)tok * KVDIM_ + (h - NH_) * D_;

    float x1 = buf[d];
    float x2 = buf[d + D_ / 2];
    buf[d]           = x1 * c1 - x2 * s1;
    buf[d + D_ / 2]  = x2 * c2 + x1 * s2;
}

// ---------------- block-sparse attention (mma.sync, 3xTF32) -----------------
#define LDQ_   132
#define LDSS_  68
#define AT_SMEM_FLOATS (64*LDQ_ + 64*LDQ_ + 64*LDSS_ + 128 + 128 + 3*64)
#define AT_SMEM_BYTES  (AT_SMEM_FLOATS * 4)

__global__ void __launch_bounds__(256, 2)
attn_kernel()
{
    extern __shared__ float sm[];
    float* Qs   = sm;
    float* KVs  = Qs + 64 * LDQ_;
    float* Ss   = KVs + 64 * LDQ_;
    float* wmax = Ss + 64 * LDSS_;
    float* wsum = wmax + 128;
    float* rowm = wsum + 128;
    float* rowl = rowm + 64;
    float* rowf = rowl + 64;
    __shared__ int sel_s[NSEL_];
    __shared__ int keep_s[NSEL_];

    const int qid = blockIdx.x;
    const int h   = blockIdx.y;
    const int b   = blockIdx.z;
    const int t   = threadIdx.x;
    const int kvh = h / (NH_ / NKV_);

    const int warp = t >> 5, lane = t & 31;
    const int g  = lane >> 2;
    const int tg = lane & 3;
    const int wm  = (warp >> 1) * 16;
    const int nh  = warp & 1;
    const int wn  = nh * 32;
    const int wn2 = nh * 64;
    const int row0 = wm + g;
    const int row1 = wm + g + 8;

    const float* qptr = g_q + ((size_t)(b * S_ + qid * BS_)) * QDIM_ + h * D_;
    for (int i4 = t; i4 < 64 * 32; i4 += 256) {
        int r = i4 >> 5, d4 = (i4 & 31) << 2;
        *(float4*)&Qs[r * LDQ_ + d4] = *(const float4*)(qptr + (size_t)r * QDIM_ + d4);
    }

    if (t < NSEL_) {
        int s;
        if (t < NGLOB_) { s = t * STRIDE_; if (s > KB_ - 1) s = KB_ - 1; }
        else            { int j = t - NGLOB_; s = qid - (NLOCAL_ - 1) + j;
                          s = s < 0 ? 0 : (s > KB_ - 1 ? KB_ - 1 : s); }
        bool valid = (s <= qid);
        bool dup = false;
        for (int jj = 0; jj < t; jj++) {
            int sj;
            if (jj < NGLOB_) { sj = jj * STRIDE_; if (sj > KB_ - 1) sj = KB_ - 1; }
            else             { int j2 = jj - NGLOB_; sj = qid - (NLOCAL_ - 1) + j2;
                               sj = sj < 0 ? 0 : (sj > KB_ - 1 ? KB_ - 1 : sj); }
            if (sj == s) dup = true;
        }
        sel_s[t]  = s;
        keep_s[t] = (valid && !dup) ? 1 : 0;
    }
    if (t < 64) { rowm[t] = -1e30f; rowl[t] = 0.0f; }

    float o[8][4];
#pragma unroll
    for (int ni = 0; ni < 8; ni++)
#pragma unroll
        for (int c = 0; c < 4; c++) o[ni][c] = 0.0f;

    __syncthreads();

    for (int bi = 0; bi < NSEL_; bi++) {
        if (!keep_s[bi]) continue;
        const int kblk = sel_s[bi];
        const bool diag = (kblk == qid);

        const float* kptr = g_k + ((size_t)(b * S_ + kblk * BS_)) * KVDIM_ + kvh * D_;
        for (int i4 = t; i4 < 64 * 32; i4 += 256) {
            int r = i4 >> 5, d4 = (i4 & 31) << 2;
            *(float4*)&KVs[r * LDQ_ + d4] = *(const float4*)(kptr + (size_t)r * KVDIM_ + d4);
        }
        __syncthreads();

        float sacc[4][4];
#pragma unroll
        for (int ni = 0; ni < 4; ni++)
#pragma unroll
            for (int c = 0; c < 4; c++) sacc[ni][c] = 0.0f;

#pragma unroll
        for (int ks = 0; ks < 16; ks++) {
            const int kb = ks * 8;
            uint32_t ahi[4], alo[4];
            split_tf32(Qs[row0 * LDQ_ + kb + tg],     ahi[0], alo[0]);
            split_tf32(Qs[row1 * LDQ_ + kb + tg],     ahi[1], alo[1]);
            split_tf32(Qs[row0 * LDQ_ + kb + tg + 4], ahi[2], alo[2]);
            split_tf32(Qs[row1 * LDQ_ + kb + tg + 4], ahi[3], alo[3]);
#pragma unroll
            for (int ni = 0; ni < 4; ni++) {
                const int n = wn + ni * 8 + g;
                uint32_t bhi[2], blo[2];
                split_tf32(KVs[n * LDQ_ + kb + tg],     bhi[0], blo[0]);
                split_tf32(KVs[n * LDQ_ + kb + tg + 4], bhi[1], blo[1]);
                mma_tf32(sacc[ni], ahi, bhi);
                mma_tf32(sacc[ni], ahi, blo);
                mma_tf32(sacc[ni], alo, bhi);
            }
        }

        float pm0 = -1e30f, pm1 = -1e30f;
#pragma unroll
        for (int ni = 0; ni < 4; ni++) {
            const int colb = wn + ni * 8 + 2 * tg;
#pragma unroll
            for (int c = 0; c < 4; c++) {
                const int col = colb + (c & 1);
                const int row = (c < 2) ? row0 : row1;
                float v = sacc[ni][c] * SCALE_;
                if (diag && col > row) v += NEG_;
                sacc[ni][c] = v;
                if (c < 2) pm0 = fmaxf(pm0, v);
                else       pm1 = fmaxf(pm1, v);
            }
        }
        pm0 = fmaxf(pm0, __shfl_xor_sync(0xffffffff, pm0, 1));
        pm0 = fmaxf(pm0, __shfl_xor_sync(0xffffffff, pm0, 2));
        pm1 = fmaxf(pm1, __shfl_xor_sync(0xffffffff, pm1, 1));
        pm1 = fmaxf(pm1, __shfl_xor_sync(0xffffffff, pm1, 2));
        if (tg == 0) {
            wmax[nh * 64 + row0] = pm0;
            wmax[nh * 64 + row1] = pm1;
        }
        __syncthreads();

        float mx0 = fmaxf(fmaxf(wmax[row0], wmax[64 + row0]), rowm[row0]);
        float mx1 = fmaxf(fmaxf(wmax[row1], wmax[64 + row1]), rowm[row1]);
        float ps0 = 0.0f, ps1 = 0.0f;
#pragma unroll
        for (int ni = 0; ni < 4; ni++) {
#pragma unroll
            for (int c = 0; c < 4; c++) {
                float p = __expf(sacc[ni][c] - ((c < 2) ? mx0 : mx1));
                sacc[ni][c] = p;
                if (c < 2) ps0 += p; else ps1 += p;
            }
        }
        ps0 += __shfl_xor_sync(0xffffffff, ps0, 1);
        ps0 += __shfl_xor_sync(0xffffffff, ps0, 2);
        ps1 += __shfl_xor_sync(0xffffffff, ps1, 1);
        ps1 += __shfl_xor_sync(0xffffffff, ps1, 2);
        if (tg == 0) {
            wsum[nh * 64 + row0] = ps0;
            wsum[nh * 64 + row1] = ps1;
        }
        float mxt = 0.0f, ft = 0.0f;
        if (t < 64) {
            mxt = fmaxf(fmaxf(wmax[t], wmax[64 + t]), rowm[t]);
            ft  = __expf(rowm[t] - mxt);
            rowf[t] = ft;
        }
        __syncthreads();

        if (t < 64) {
            rowl[t] = rowl[t] * ft + wsum[t] + wsum[64 + t];
            rowm[t] = mxt;
        }

        {
            float f0 = rowf[row0], f1 = rowf[row1];
#pragma unroll
            for (int ni = 0; ni < 8; ni++) {
                o[ni][0] *= f0; o[ni][1] *= f0;
                o[ni][2] *= f1; o[ni][3] *= f1;
            }
        }
#pragma unroll
        for (int ni = 0; ni < 4; ni++) {
            const int colb = wn + ni * 8 + 2 * tg;
            *(float2*)&Ss[row0 * LDSS_ + colb] = make_float2(sacc[ni][0], sacc[ni][1]);
            *(float2*)&Ss[row1 * LDSS_ + colb] = make_float2(sacc[ni][2], sacc[ni][3]);
        }
        const float* vptr = g_v + ((size_t)(b * S_ + kblk * BS_)) * KVDIM_ + kvh * D_;
        for (int i4 = t; i4 < 64 * 32; i4 += 256) {
            int r = i4 >> 5, d4 = (i4 & 31) << 2;
            *(float4*)&KVs[r * LDQ_ + d4] = *(const float4*)(vptr + (size_t)r * KVDIM_ + d4);
        }
        __syncthreads();

#pragma unroll
        for (int ks = 0; ks < 8; ks++) {
            const int kb = ks * 8;
            uint32_t ahi[4], alo[4];
            split_tf32(Ss[row0 * LDSS_ + kb + tg],     ahi[0], alo[0]);
            split_tf32(Ss[row1 * LDSS_ + kb + tg],     ahi[1], alo[1]);
            split_tf32(Ss[row0 * LDSS_ + kb + tg + 4], ahi[2], alo[2]);
            split_tf32(Ss[row1 * LDSS_ + kb + tg + 4], ahi[3], alo[3]);
#pragma unroll
            for (int ni = 0; ni < 8; ni++) {
                const int n = wn2 + ni * 8 + g;
                uint32_t bhi[2], blo[2];
                split_tf32(KVs[(kb + tg) * LDQ_ + n],     bhi[0], blo[0]);
                split_tf32(KVs[(kb + tg + 4) * LDQ_ + n], bhi[1], blo[1]);
                mma_tf32(o[ni], ahi, bhi);
                mma_tf32(o[ni], ahi, blo);
                mma_tf32(o[ni], alo, bhi);
            }
        }
        __syncthreads();
    }

    const float invl0 = 1.0f / rowl[row0];
    const float invl1 = 1.0f / rowl[row1];
    float* ob0 = g_attn + ((size_t)(b * S_ + qid * BS_ + row0)) * QDIM_ + h * D_;
    float* ob1 = g_attn + ((size_t)(b * S_ + qid * BS_ + row1)) * QDIM_ + h * D_;
#pragma unroll
    for (int ni = 0; ni < 8; ni++) {
        const int col = wn2 + ni * 8 + 2 * tg;
        *(uint2*)(ob0 + col) = make_uint2(f2tf32(o[ni][0] * invl0),
                                          f2tf32(o[ni][1] * invl0));
        *(uint2*)(ob1 + col) = make_uint2(f2tf32(o[ni][2] * invl1),
                                          f2tf32(o[ni][3] * invl1));
    }
}

// ---------------- host launcher ---------------------------------------------
extern "C" void kernel_launch(void* const* d_in, const int* in_sizes, int n_in,
                              void* d_out, int out_size)
{
    const float* X    = (const float*)d_in[0];
    const float* cosp = (const float*)d_in[1];
    const float* sinp = (const float*)d_in[2];
    const float* Wq   = (const float*)d_in[3];
    const float* Wk   = (const float*)d_in[4];
    const float* Wv   = (const float*)d_in[5];
    const float* Wo   = (const float*)d_in[6];
    float* out = (float*)d_out;

    float *qb, *kb, *vb, *ab;
    uint32_t *xt, *wt;
    cudaGetSymbolAddress((void**)&qb, g_q);
    cudaGetSymbolAddress((void**)&kb, g_k);
    cudaGetSymbolAddress((void**)&vb, g_v);
    cudaGetSymbolAddress((void**)&ab, g_attn);
    cudaGetSymbolAddress((void**)&xt, g_xt);
    cudaGetSymbolAddress((void**)&wt, g_wt);

    cudaFuncSetAttribute(attn_kernel,
                         cudaFuncAttributeMaxDynamicSharedMemorySize,
                         AT_SMEM_BYTES);
    cudaFuncSetAttribute(gemm_tf32_pipe,
                         cudaFuncAttributeMaxDynamicSharedMemorySize,
                         GSMEM_BYTES);

    const int BIG = 1 << 30;

    // one pass: X + all weights -> tf32
    cvt_all_kernel<<<(CVT_TOT4_ + 255) / 256, 256>>>(X, Wq, Wk, Wv, Wo);

    // Q projection: [8192 x 2048]
    gemm_tf32_pipe<<<dim3(QDIM_ / 128, NTOK_ / 128), 256, GSMEM_BYTES>>>(
        xt, wt + WQ_OFF_, qb, qb, BIG, QDIM_, H_);

    // fused K+V projection: weights contiguous [1024 x 2048]; split at col 512
    gemm_tf32_pipe<<<dim3(2 * KVDIM_ / 128, NTOK_ / 128), 256, GSMEM_BYTES>>>(
        xt, wt + WK_OFF_, kb, vb, KVDIM_, KVDIM_, H_);

    // RoPE on Q and K
    int rope_total = NTOK_ * (NH_ + NKV_) * (D_ / 2);
    rope_kernel<<<(rope_total + 255) / 256, 256>>>(cosp, sinp);

    // block-sparse attention (writes tf32 bits to g_attn)
    attn_kernel<<<dim3(KB_, NH_, B_), 256, AT_SMEM_BYTES>>>();

    // O projection
    gemm_tf32_pipe<<<dim3(H_ / 128, NTOK_ / 128), 256, GSMEM_BYTES>>>(
        (const uint32_t*)ab, wt + WO_OFF_, out, out, BIG, H_, QDIM_);
}

// round 12
// speedup vs baseline: 1.4680x; 1.3809x over previous
#include <cuda_runtime.h>
#include <cuda_fp16.h>
#include <cstdint>

// ---------------- problem constants ----------------
#define B_      2
#define S_      4096
#define H_      2048
#define NH_     16
#define NKV_    4
#define D_      128
#define BS_     64
#define KB_     (S_ / BS_)
#define NGLOB_  4
#define NLOCAL_ 8
#define NSEL_   (NGLOB_ + NLOCAL_)
#define STRIDE_ 16
#define NTOK_   (B_ * S_)       // 8192
#define QDIM_   (NH_ * D_)      // 2048
#define KVDIM_  (NKV_ * D_)     // 512
#define SCALE_  0.088388347648318447f
#define NEG_    (-1000000000.0f)

// ---------------- scratch ---------------------------------------------------
__device__ float  g_q[(size_t)NTOK_ * QDIM_];
__device__ float  g_k[(size_t)NTOK_ * KVDIM_];
__device__ float  g_v[(size_t)NTOK_ * KVDIM_];
__device__ __half g_attn[(size_t)NTOK_ * QDIM_];      // attention out (fp16)
__device__ __half g_xh[(size_t)NTOK_ * H_];           // X in fp16
// weights fp16: [Wq 4M][Wk 1M][Wv 1M][Wo 4M] halves
#define WQ_OFF_ 0
#define WK_OFF_ ((size_t)QDIM_ * H_)
#define WV_OFF_ (WK_OFF_ + (size_t)KVDIM_ * H_)
#define WO_OFF_ (WV_OFF_ + (size_t)KVDIM_ * H_)
#define WH_HALVES_ (WO_OFF_ + (size_t)QDIM_ * H_)
__device__ __half g_wh[WH_HALVES_];

// ---------------- helpers ---------------------------------------------------
__device__ __forceinline__ uint32_t f2tf32(float x) {
    uint32_t u;
    asm("cvt.rna.tf32.f32 %0, %1;" : "=r"(u) : "f"(x));
    return u;
}
__device__ __forceinline__ void split_tf32(float x, uint32_t& hi, uint32_t& lo) {
    hi = f2tf32(x);
    lo = f2tf32(x - __uint_as_float(hi));
}
__device__ __forceinline__ void mma_tf32(float* c, const uint32_t* a, const uint32_t* b) {
    asm volatile(
        "mma.sync.aligned.m16n8k8.row.col.f32.tf32.tf32.f32 "
        "{%0,%1,%2,%3}, {%4,%5,%6,%7}, {%8,%9}, {%0,%1,%2,%3};\n"
        : "+f"(c[0]), "+f"(c[1]), "+f"(c[2]), "+f"(c[3])
        : "r"(a[0]), "r"(a[1]), "r"(a[2]), "r"(a[3]), "r"(b[0]), "r"(b[1]));
}
__device__ __forceinline__ void mma_f16_k16(float* c, const uint32_t* a, const uint32_t* b) {
    asm volatile(
        "mma.sync.aligned.m16n8k16.row.col.f32.f16.f16.f32 "
        "{%0,%1,%2,%3}, {%4,%5,%6,%7}, {%8,%9}, {%0,%1,%2,%3};\n"
        : "+f"(c[0]), "+f"(c[1]), "+f"(c[2]), "+f"(c[3])
        : "r"(a[0]), "r"(a[1]), "r"(a[2]), "r"(a[3]), "r"(b[0]), "r"(b[1]));
}
__device__ __forceinline__ void cp_async16(uint32_t saddr, const void* gptr) {
    asm volatile("cp.async.cg.shared.global [%0], [%1], 16;\n"
                 :: "r"(saddr), "l"(gptr));
}

// ---------------- merged fp32 -> fp16 conversion ----------------------------
#define CVT_X4_   (NTOK_ * (H_ / 4))
#define CVT_WQ4_  (QDIM_ * (H_ / 4))
#define CVT_WK4_  (KVDIM_ * (H_ / 4))
#define CVT_TOT4_ (CVT_X4_ + CVT_WQ4_ + 2 * CVT_WK4_ + CVT_WQ4_)

__global__ void cvt_all_kernel(const float* __restrict__ X,
                               const float* __restrict__ Wq,
                               const float* __restrict__ Wk,
                               const float* __restrict__ Wv,
                               const float* __restrict__ Wo)
{
    int i = blockIdx.x * blockDim.x + threadIdx.x;
    if (i >= CVT_TOT4_) return;

    const float4* src;
    uint2* dst;
    if (i < CVT_X4_) {
        src = (const float4*)X + i;
        dst = (uint2*)g_xh + i;
    } else if (i < CVT_X4_ + CVT_WQ4_) {
        int j = i - CVT_X4_;
        src = (const float4*)Wq + j;
        dst = (uint2*)(g_wh + WQ_OFF_) + j;
    } else if (i < CVT_X4_ + CVT_WQ4_ + CVT_WK4_) {
        int j = i - CVT_X4_ - CVT_WQ4_;
        src = (const float4*)Wk + j;
        dst = (uint2*)(g_wh + WK_OFF_) + j;
    } else if (i < CVT_X4_ + CVT_WQ4_ + 2 * CVT_WK4_) {
        int j = i - CVT_X4_ - CVT_WQ4_ - CVT_WK4_;
        src = (const float4*)Wv + j;
        dst = (uint2*)(g_wh + WV_OFF_) + j;
    } else {
        int j = i - CVT_X4_ - CVT_WQ4_ - 2 * CVT_WK4_;
        src = (const float4*)Wo + j;
        dst = (uint2*)(g_wh + WO_OFF_) + j;
    }
    float4 v = *src;
    __half2 h0 = __floats2half2_rn(v.x, v.y);
    __half2 h1 = __floats2half2_rn(v.z, v.w);
    uint2 o;
    o.x = *(uint32_t*)&h0;
    o.y = *(uint32_t*)&h1;
    *dst = o;
}

// ---------------- pipelined fp16 GEMM ---------------------------------------
//  C[M,N] = A[M,K] @ B[N,K]^T ; A,B fp16, K contiguous.
//  128x128 CTA tile, BK=32 halves, 4-stage cp.async, 256 threads = 8 warps
//  (2x4), warp tile 64x32 (4x4 m16n8k16). Cols >= Nsplit go to C1.
//  smem rows: 32 halves + 8 pad = 40 halves = 20 words (same indexing as tf32).
#define BKH_  32
#define LDHW_ 20                                 // words per smem row
#define GSTG_ 4
#define ST_WORDS_ (2 * 128 * LDHW_)              // A+B per stage = 5120 words
#define GSMEM_BYTES (GSTG_ * ST_WORDS_ * 4)      // 81920

__global__ void __launch_bounds__(256, 2)
gemm_f16_pipe(const __half* __restrict__ A, const __half* __restrict__ B,
              float* __restrict__ C0, float* __restrict__ C1,
              int Nsplit, int ldc, int K)
{
    extern __shared__ uint32_t smg[];

    const size_t bm = (size_t)blockIdx.y * 128;
    const size_t bn = (size_t)blockIdx.x * 128;
    const int t = threadIdx.x;
    const int lane = t & 31, warp = t >> 5;
    const int g  = lane >> 2, tg = lane & 3;
    const int wm = (warp >> 2) * 64;
    const int wn = (warp & 3) * 32;

    float acc[4][4][4];
#pragma unroll
    for (int mi = 0; mi < 4; mi++)
#pragma unroll
        for (int ni = 0; ni < 4; ni++)
#pragma unroll
            for (int c = 0; c < 4; c++) acc[mi][ni][c] = 0.0f;

    auto load_stage = [&](int s, int i) {
        uint32_t* as = smg + s * ST_WORDS_;
        uint32_t* bs = as + 128 * LDHW_;
        const int k0 = i * BKH_;
#pragma unroll
        for (int j = 0; j < 2; j++) {
            int idx = t + j * 256;
            int row = idx >> 2, c4 = idx & 3;    // 4 x 16B chunks per 64B row
            uint32_t sa = (uint32_t)__cvta_generic_to_shared(&as[row * LDHW_ + c4 * 4]);
            cp_async16(sa, A + (bm + row) * (size_t)K + k0 + c4 * 8);
            uint32_t sb = (uint32_t)__cvta_generic_to_shared(&bs[row * LDHW_ + c4 * 4]);
            cp_async16(sb, B + (bn + row) * (size_t)K + k0 + c4 * 8);
        }
        asm volatile("cp.async.commit_group;\n");
    };

    auto compute_stage = [&](int s) {
        const uint32_t* as = smg + s * ST_WORDS_;
        const uint32_t* bs = as + 128 * LDHW_;
#pragma unroll
        for (int kk = 0; kk < 2; kk++) {
            const int kb = kk * 8;               // word offset (16 halves)
            uint32_t a[4][4];
#pragma unroll
            for (int mi = 0; mi < 4; mi++) {
                const int m0 = wm + mi * 16;
                a[mi][0] = as[(m0 + g) * LDHW_ + kb + tg];
                a[mi][1] = as[(m0 + g + 8) * LDHW_ + kb + tg];
                a[mi][2] = as[(m0 + g) * LDHW_ + kb + tg + 4];
                a[mi][3] = as[(m0 + g + 8) * LDHW_ + kb + tg + 4];
            }
            uint32_t bf[4][2];
#pragma unroll
            for (int ni = 0; ni < 4; ni++) {
                const int n0 = wn + ni * 8;
                bf[ni][0] = bs[(n0 + g) * LDHW_ + kb + tg];
                bf[ni][1] = bs[(n0 + g) * LDHW_ + kb + tg + 4];
            }
#pragma unroll
            for (int mi = 0; mi < 4; mi++)
#pragma unroll
                for (int ni = 0; ni < 4; ni++)
                    mma_f16_k16(acc[mi][ni], a[mi], bf[ni]);
        }
    };

    const int niter = K / BKH_;
    load_stage(0, 0);
    load_stage(1, 1);
    load_stage(2, 2);

    for (int i = 0; i < niter - 1; i++) {
        asm volatile("cp.async.wait_group 2;\n" ::: "memory");
        __syncthreads();
        if (i + 3 < niter) load_stage((i + 3) % GSTG_, i + 3);
        compute_stage(i % GSTG_);
    }
    asm volatile("cp.async.wait_group 0;\n" ::: "memory");
    __syncthreads();
    compute_stage((niter - 1) % GSTG_);

    float* C = C0;
    int cb = (int)bn;
    if (cb >= Nsplit) { C = C1; cb -= Nsplit; }

#pragma unroll
    for (int mi = 0; mi < 4; mi++) {
        const size_t row = bm + wm + mi * 16 + g;
#pragma unroll
        for (int ni = 0; ni < 4; ni++) {
            const int col = cb + wn + ni * 8 + 2 * tg;
            float* cp0 = C + row * ldc + col;
            float* cp1 = cp0 + (size_t)8 * ldc;
            *(float2*)cp0 = make_float2(acc[mi][ni][0], acc[mi][ni][1]);
            *(float2*)cp1 = make_float2(acc[mi][ni][2], acc[mi][ni][3]);
        }
    }
}

// ---------------- RoPE (in-place on g_q, g_k) -------------------------------
__global__ void rope_kernel(const float* __restrict__ cosp,
                            const float* __restrict__ sinp)
{
    int idx = blockIdx.x * blockDim.x + threadIdx.x;
    const int total = NTOK_ * (NH_ + NKV_) * (D_ / 2);
    if (idx >= total) return;

    int d    = idx % (D_ / 2);
    int rest = idx / (D_ / 2);
    int h    = rest % (NH_ + NKV_);
    int tok  = rest / (NH_ + NKV_);

    float c1 = cosp[(size_t)tok * D_ + d];
    float s1 = sinp[(size_t)tok * D_ + d];
    float c2 = cosp[(size_t)tok * D_ + d + D_ / 2];
    float s2 = sinp[(size_t)tok * D_ + d + D_ / 2];

    float* buf;
    if (h < NH_) buf = g_q + (size_t)tok * QDIM_ + h * D_;
    else         buf = g_k + (size_t)tok * KVDIM_ + (h - NH_) * D_;

    float x1 = buf[d];
    float x2 = buf[d + D_ / 2];
    buf[d]           = x1 * c1 - x2 * s1;
    buf[d + D_ / 2]  = x2 * c2 + x1 * s2;
}

// ---------------- block-sparse attention (mma.sync, 3xTF32) -----------------
#define LDQ_   132
#define LDSS_  68
#define AT_SMEM_FLOATS (64*LDQ_ + 64*LDQ_ + 64*LDSS_ + 128 + 128 + 3*64)
#define AT_SMEM_BYTES  (AT_SMEM_FLOATS * 4)

__global__ void __launch_bounds__(256, 2)
attn_kernel()
{
    extern __shared__ float sm[];
    float* Qs   = sm;
    float* KVs  = Qs + 64 * LDQ_;
    float* Ss   = KVs + 64 * LDQ_;
    float* wmax = Ss + 64 * LDSS_;
    float* wsum = wmax + 128;
    float* rowm = wsum + 128;
    float* rowl = rowm + 64;
    float* rowf = rowl + 64;
    __shared__ int sel_s[NSEL_];
    __shared__ int keep_s[NSEL_];

    const int qid = blockIdx.x;
    const int h   = blockIdx.y;
    const int b   = blockIdx.z;
    const int t   = threadIdx.x;
    const int kvh = h / (NH_ / NKV_);

    const int warp = t >> 5, lane = t & 31;
    const int g  = lane >> 2;
    const int tg = lane & 3;
    const int wm  = (warp >> 1) * 16;
    const int nh  = warp & 1;
    const int wn  = nh * 32;
    const int wn2 = nh * 64;
    const int row0 = wm + g;
    const int row1 = wm + g + 8;

    const float* qptr = g_q + ((size_t)(b * S_ + qid * BS_)) * QDIM_ + h * D_;
    for (int i4 = t; i4 < 64 * 32; i4 += 256) {
        int r = i4 >> 5, d4 = (i4 & 31) << 2;
        *(float4*)&Qs[r * LDQ_ + d4] = *(const float4*)(qptr + (size_t)r * QDIM_ + d4);
    }

    if (t < NSEL_) {
        int s;
        if (t < NGLOB_) { s = t * STRIDE_; if (s > KB_ - 1) s = KB_ - 1; }
        else            { int j = t - NGLOB_; s = qid - (NLOCAL_ - 1) + j;
                          s = s < 0 ? 0 : (s > KB_ - 1 ? KB_ - 1 : s); }
        bool valid = (s <= qid);
        bool dup = false;
        for (int jj = 0; jj < t; jj++) {
            int sj;
            if (jj < NGLOB_) { sj = jj * STRIDE_; if (sj > KB_ - 1) sj = KB_ - 1; }
            else             { int j2 = jj - NGLOB_; sj = qid - (NLOCAL_ - 1) + j2;
                               sj = sj < 0 ? 0 : (sj > KB_ - 1 ? KB_ - 1 : sj); }
            if (sj == s) dup = true;
        }
        sel_s[t]  = s;
        keep_s[t] = (valid && !dup) ? 1 : 0;
    }
    if (t < 64) { rowm[t] = -1e30f; rowl[t] = 0.0f; }

    float o[8][4];
#pragma unroll
    for (int ni = 0; ni < 8; ni++)
#pragma unroll
        for (int c = 0; c < 4; c++) o[ni][c] = 0.0f;

    __syncthreads();

    for (int bi = 0; bi < NSEL_; bi++) {
        if (!keep_s[bi]) continue;
        const int kblk = sel_s[bi];
        const bool diag = (kblk == qid);

        const float* kptr = g_k + ((size_t)(b * S_ + kblk * BS_)) * KVDIM_ + kvh * D_;
        for (int i4 = t; i4 < 64 * 32; i4 += 256) {
            int r = i4 >> 5, d4 = (i4 & 31) << 2;
            *(float4*)&KVs[r * LDQ_ + d4] = *(const float4*)(kptr + (size_t)r * KVDIM_ + d4);
        }
        __syncthreads();

        float sacc[4][4];
#pragma unroll
        for (int ni = 0; ni < 4; ni++)
#pragma unroll
            for (int c = 0; c < 4; c++) sacc[ni][c] = 0.0f;

#pragma unroll
        for (int ks = 0; ks < 16; ks++) {
            const int kb = ks * 8;
            uint32_t ahi[4], alo[4];
            split_tf32(Qs[row0 * LDQ_ + kb + tg],     ahi[0], alo[0]);
            split_tf32(Qs[row1 * LDQ_ + kb + tg],     ahi[1], alo[1]);
            split_tf32(Qs[row0 * LDQ_ + kb + tg + 4], ahi[2], alo[2]);
            split_tf32(Qs[row1 * LDQ_ + kb + tg + 4], ahi[3], alo[3]);
#pragma unroll
            for (int ni = 0; ni < 4; ni++) {
                const int n = wn + ni * 8 + g;
                uint32_t bhi[2], blo[2];
                split_tf32(KVs[n * LDQ_ + kb + tg],     bhi[0], blo[0]);
                split_tf32(KVs[n * LDQ_ + kb + tg + 4], bhi[1], blo[1]);
                mma_tf32(sacc[ni], ahi, bhi);
                mma_tf32(sacc[ni], ahi, blo);
                mma_tf32(sacc[ni], alo, bhi);
            }
        }

        float pm0 = -1e30f, pm1 = -1e30f;
#pragma unroll
        for (int ni = 0; ni < 4; ni++) {
            const int colb = wn + ni * 8 + 2 * tg;
#pragma unroll
            for (int c = 0; c < 4; c++) {
                const int col = colb + (c & 1);
                const int row = (c < 2) ? row0 : row1;
                float v = sacc[ni][c] * SCALE_;
                if (diag && col > row) v += NEG_;
                sacc[ni][c] = v;
                if (c < 2) pm0 = fmaxf(pm0, v);
                else       pm1 = fmaxf(pm1, v);
            }
        }
        pm0 = fmaxf(pm0, __shfl_xor_sync(0xffffffff, pm0, 1));
        pm0 = fmaxf(pm0, __shfl_xor_sync(0xffffffff, pm0, 2));
        pm1 = fmaxf(pm1, __shfl_xor_sync(0xffffffff, pm1, 1));
        pm1 = fmaxf(pm1, __shfl_xor_sync(0xffffffff, pm1, 2));
        if (tg == 0) {
            wmax[nh * 64 + row0] = pm0;
            wmax[nh * 64 + row1] = pm1;
        }
        __syncthreads();

        float mx0 = fmaxf(fmaxf(wmax[row0], wmax[64 + row0]), rowm[row0]);
        float mx1 = fmaxf(fmaxf(wmax[row1], wmax[64 + row1]), rowm[row1]);
        float ps0 = 0.0f, ps1 = 0.0f;
#pragma unroll
        for (int ni = 0; ni < 4; ni++) {
#pragma unroll
            for (int c = 0; c < 4; c++) {
                float p = __expf(sacc[ni][c] - ((c < 2) ? mx0 : mx1));
                sacc[ni][c] = p;
                if (c < 2) ps0 += p; else ps1 += p;
            }
        }
        ps0 += __shfl_xor_sync(0xffffffff, ps0, 1);
        ps0 += __shfl_xor_sync(0xffffffff, ps0, 2);
        ps1 += __shfl_xor_sync(0xffffffff, ps1, 1);
        ps1 += __shfl_xor_sync(0xffffffff, ps1, 2);
        if (tg == 0) {
            wsum[nh * 64 + row0] = ps0;
            wsum[nh * 64 + row1] = ps1;
        }
        float mxt = 0.0f, ft = 0.0f;
        if (t < 64) {
            mxt = fmaxf(fmaxf(wmax[t], wmax[64 + t]), rowm[t]);
            ft  = __expf(rowm[t] - mxt);
            rowf[t] = ft;
        }
        __syncthreads();

        if (t < 64) {
            rowl[t] = rowl[t] * ft + wsum[t] + wsum[64 + t];
            rowm[t] = mxt;
        }

        {
            float f0 = rowf[row0], f1 = rowf[row1];
#pragma unroll
            for (int ni = 0; ni < 8; ni++) {
                o[ni][0] *= f0; o[ni][1] *= f0;
                o[ni][2] *= f1; o[ni][3] *= f1;
            }
        }
#pragma unroll
        for (int ni = 0; ni < 4; ni++) {
            const int colb = wn + ni * 8 + 2 * tg;
            *(float2*)&Ss[row0 * LDSS_ + colb] = make_float2(sacc[ni][0], sacc[ni][1]);
            *(float2*)&Ss[row1 * LDSS_ + colb] = make_float2(sacc[ni][2], sacc[ni][3]);
        }
        const float* vptr = g_v + ((size_t)(b * S_ + kblk * BS_)) * KVDIM_ + kvh * D_;
        for (int i4 = t; i4 < 64 * 32; i4 += 256) {
            int r = i4 >> 5, d4 = (i4 & 31) << 2;
            *(float4*)&KVs[r * LDQ_ + d4] = *(const float4*)(vptr + (size_t)r * KVDIM_ + d4);
        }
        __syncthreads();

#pragma unroll
        for (int ks = 0; ks < 8; ks++) {
            const int kb = ks * 8;
            uint32_t ahi[4], alo[4];
            split_tf32(Ss[row0 * LDSS_ + kb + tg],     ahi[0], alo[0]);
            split_tf32(Ss[row1 * LDSS_ + kb + tg],     ahi[1], alo[1]);
            split_tf32(Ss[row0 * LDSS_ + kb + tg + 4], ahi[2], alo[2]);
            split_tf32(Ss[row1 * LDSS_ + kb + tg + 4], ahi[3], alo[3]);
#pragma unroll
            for (int ni = 0; ni < 8; ni++) {
                const int n = wn2 + ni * 8 + g;
                uint32_t bhi[2], blo[2];
                split_tf32(KVs[(kb + tg) * LDQ_ + n],     bhi[0], blo[0]);
                split_tf32(KVs[(kb + tg + 4) * LDQ_ + n], bhi[1], blo[1]);
                mma_tf32(o[ni], ahi, bhi);
                mma_tf32(o[ni], ahi, blo);
                mma_tf32(o[ni], alo, bhi);
            }
        }
        __syncthreads();
    }

    // finalize: divide by denom, write out as fp16 (feeds O projection)
    const float invl0 = 1.0f / rowl[row0];
    const float invl1 = 1.0f / rowl[row1];
    __half* ob0 = g_attn + ((size_t)(b * S_ + qid * BS_ + row0)) * QDIM_ + h * D_;
    __half* ob1 = g_attn + ((size_t)(b * S_ + qid * BS_ + row1)) * QDIM_ + h * D_;
#pragma unroll
    for (int ni = 0; ni < 8; ni++) {
        const int col = wn2 + ni * 8 + 2 * tg;
        __half2 h0 = __floats2half2_rn(o[ni][0] * invl0, o[ni][1] * invl0);
        __half2 h1 = __floats2half2_rn(o[ni][2] * invl1, o[ni][3] * invl1);
        *(__half2*)(ob0 + col) = h0;
        *(__half2*)(ob1 + col) = h1;
    }
}

// ---------------- host launcher ---------------------------------------------
extern "C" void kernel_launch(void* const* d_in, const int* in_sizes, int n_in,
                              void* d_out, int out_size)
{
    const float* X    = (const float*)d_in[0];
    const float* cosp = (const float*)d_in[1];
    const float* sinp = (const float*)d_in[2];
    const float* Wq   = (const float*)d_in[3];
    const float* Wk   = (const float*)d_in[4];
    const float* Wv   = (const float*)d_in[5];
    const float* Wo   = (const float*)d_in[6];
    float* out = (float*)d_out;

    float *qb, *kb, *vb;
    __half *ab, *xh, *wh;
    cudaGetSymbolAddress((void**)&qb, g_q);
    cudaGetSymbolAddress((void**)&kb, g_k);
    cudaGetSymbolAddress((void**)&vb, g_v);
    cudaGetSymbolAddress((void**)&ab, g_attn);
    cudaGetSymbolAddress((void**)&xh, g_xh);
    cudaGetSymbolAddress((void**)&wh, g_wh);

    cudaFuncSetAttribute(attn_kernel,
                         cudaFuncAttributeMaxDynamicSharedMemorySize,
                         AT_SMEM_BYTES);
    cudaFuncSetAttribute(gemm_f16_pipe,
                         cudaFuncAttributeMaxDynamicSharedMemorySize,
                         GSMEM_BYTES);

    const int BIG = 1 << 30;

    // one pass: X + all weights -> fp16
    cvt_all_kernel<<<(CVT_TOT4_ + 255) / 256, 256>>>(X, Wq, Wk, Wv, Wo);

    // Q projection: [8192 x 2048]
    gemm_f16_pipe<<<dim3(QDIM_ / 128, NTOK_ / 128), 256, GSMEM_BYTES>>>(
        xh, wh + WQ_OFF_, qb, qb, BIG, QDIM_, H_);

    // fused K+V projection: weights contiguous [1024 x 2048]; split at col 512
    gemm_f16_pipe<<<dim3(2 * KVDIM_ / 128, NTOK_ / 128), 256, GSMEM_BYTES>>>(
        xh, wh + WK_OFF_, kb, vb, KVDIM_, KVDIM_, H_);

    // RoPE on Q and K
    int rope_total = NTOK_ * (NH_ + NKV_) * (D_ / 2);
    rope_kernel<<<(rope_total + 255) / 256, 256>>>(cosp, sinp);

    // block-sparse attention (writes fp16 to g_attn)
    attn_kernel<<<dim3(KB_, NH_, B_), 256, AT_SMEM_BYTES>>>();

    // O projection
    gemm_f16_pipe<<<dim3(H_ / 128, NTOK_ / 128), 256, GSMEM_BYTES>>>(
        ab, wh + WO_OFF_, out, out, BIG, H_, QDIM_);
}